// round 15
// baseline (speedup 1.0000x reference)
#include <cuda_runtime.h>
#include <cuda_fp16.h>
#include <math.h>
#include <stdint.h>

#define Bsz 256
#define Tt  256
#define Isz 128
#define Hsz 512
#define Csz 10
#define NG  2048   // 4*H

// fused-kernel smem (bytes); pitch 1040B (== 16 mod 128 -> conflict-free ldsm)
#define PZ     68    // z0 pitch (floats)
#define PZ1    68    // z1 pitch (halves)
#define OFF_AS 66560                          // A buffer (after Wh2s 64*1040)
#define OFF_Z0 (OFF_AS + 66560)               // 133120
#define OFF_Z1 (OFF_Z0 + 64 * PZ * 4)         // 150528
#define OFF_WX (OFF_Z1 + 64 * PZ1 * 2)        // 159232
#define PSM    (OFF_WX + 66560)               // 225792

// gemm: 3 buffers, each A(128x144B) + B(128x144B)
#define GBUF 36864
#define GSM  (3 * GBUF)

// ---------------- scratch ----------------
__device__ __half g_Zx1[(size_t)Tt * Bsz * NG];
__device__ __half g_h1[(size_t)(Tt + 1) * Bsz * Hsz];
__device__ __half g_h2[(size_t)(Tt + 1) * Bsz * Hsz];
__device__ __half g_xT[(size_t)Tt * Bsz * Isz];
__device__ __half g_W1T[(size_t)4 * Hsz * Isz];
__device__ __half g_W2T[(size_t)4 * Hsz * Hsz];
__device__ unsigned g_bar[8];

// ---------------- helpers ----------------
__device__ __forceinline__ void mma16(float* c, const uint32_t* a, const uint32_t* b) {
    asm volatile(
        "mma.sync.aligned.m16n8k16.row.col.f32.f16.f16.f32 "
        "{%0,%1,%2,%3},{%4,%5,%6,%7},{%8,%9},{%0,%1,%2,%3};"
        : "+f"(c[0]), "+f"(c[1]), "+f"(c[2]), "+f"(c[3])
        : "r"(a[0]), "r"(a[1]), "r"(a[2]), "r"(a[3]), "r"(b[0]), "r"(b[1]));
}
__device__ __forceinline__ void ldsm4(uint32_t* r, uint32_t addr) {
    asm volatile("ldmatrix.sync.aligned.m8n8.x4.shared.b16 {%0,%1,%2,%3}, [%4];"
        : "=r"(r[0]), "=r"(r[1]), "=r"(r[2]), "=r"(r[3]) : "r"(addr));
}
__device__ __forceinline__ void ldsm2(uint32_t* r, uint32_t addr) {
    asm volatile("ldmatrix.sync.aligned.m8n8.x2.shared.b16 {%0,%1}, [%2];"
        : "=r"(r[0]), "=r"(r[1]) : "r"(addr));
}
__device__ __forceinline__ float tanha(float x) {
    float y;
    asm("tanh.approx.f32 %0, %1;" : "=f"(y) : "f"(x));
    return y;
}
__device__ __forceinline__ float sigf(float x) {
    return __fmaf_rn(0.5f, tanha(0.5f * x), 0.5f);
}
__device__ __forceinline__ uint32_t smem_u32(const void* p) {
    uint32_t a;
    asm("{ .reg .u64 t; cvta.to.shared.u64 t, %1; cvt.u32.u64 %0, t; }" : "=r"(a) : "l"(p));
    return a;
}
__device__ __forceinline__ void cp16(uint32_t dst, const void* src) {
    asm volatile("cp.async.ca.shared.global [%0], [%1], 16;" :: "r"(dst), "l"(src));
}
#define CP_COMMIT() asm volatile("cp.async.commit_group;" ::: "memory")
#define CP_WAIT(n)  asm volatile("cp.async.wait_group %0;" :: "n"(n) : "memory")

__device__ __forceinline__ void bar_arrive(unsigned* p) {
    asm volatile("red.release.gpu.global.add.u32 [%0], %1;" :: "l"(p), "r"(1u) : "memory");
}
__device__ __forceinline__ void bar_spin(unsigned* p, unsigned tgt) {
    unsigned v;
    do {
        asm volatile("ld.acquire.gpu.global.u32 %0, [%1];" : "=r"(v) : "l"(p) : "memory");
    } while (v < tgt);
}

// ---------------- init ----------------
__global__ void init_kernel() {
    int i = blockIdx.x * blockDim.x + threadIdx.x;
    if (i < Bsz * Hsz) {
        g_h1[i] = __float2half(0.f);
        g_h2[i] = __float2half(0.f);
    }
    if (i < 8) g_bar[i] = 0u;
}

// ---------------- prep: x [b][t][k] fp32 -> xT [t][b][k] fp16 ----------------
__global__ void prep_x(const float* __restrict__ x, __half* __restrict__ xT) {
    int idx = blockIdx.x * blockDim.x + threadIdx.x;
    if (idx >= Tt * Bsz * 16) return;
    int q = idx & 15;
    int b = (idx >> 4) & (Bsz - 1);
    int t = idx >> 12;
    const float* src = x + ((size_t)b * Tt + t) * Isz + q * 8;
    float4 v0 = *(const float4*)src;
    float4 v1 = *(const float4*)(src + 4);
    __half2 h0 = __floats2half2_rn(v0.x, v0.y);
    __half2 h1 = __floats2half2_rn(v0.z, v0.w);
    __half2 h2 = __floats2half2_rn(v1.x, v1.y);
    __half2 h3 = __floats2half2_rn(v1.z, v1.w);
    uint4 u;
    u.x = *(uint32_t*)&h0; u.y = *(uint32_t*)&h1;
    u.z = *(uint32_t*)&h2; u.w = *(uint32_t*)&h3;
    *(uint4*)(xT + ((size_t)t * Bsz + b) * Isz + q * 8) = u;
}

// ---------------- prep: W[g][k][h] fp32 -> WT[g][h][k] fp16 ----------------
__global__ void prep_w(const float* __restrict__ W, __half* __restrict__ WT, int K) {
    int idx = blockIdx.x * blockDim.x + threadIdx.x;
    int kp = idx % (K / 2);
    int rest = idx / (K / 2);
    int h = rest % Hsz, g = rest / Hsz;
    if (g >= 4) return;
    int k = kp * 2;
    float a = W[((size_t)g * K + k) * Hsz + h];
    float b = W[((size_t)g * K + k + 1) * Hsz + h];
    *(__half2*)(WT + ((size_t)g * Hsz + h) * K + k) = __floats2half2_rn(a, b);
}

// ---------------- big GEMM (phase 1): fp16 in/out, cp.async 3-stage, 128x128 tile ----------------
__global__ void __launch_bounds__(256)
gemm_h2(const __half* __restrict__ A,
        const __half* __restrict__ WT,
        const float* __restrict__ bias,
        __half* __restrict__ Z,
        int K) {
    extern __shared__ __align__(16) unsigned char smg[];
    const uint32_t sb = smem_u32(smg);

    const int m0 = blockIdx.y * 128, n0 = blockIdx.x * 128;
    const int gate = n0 >> 9, h0 = n0 & 511;
    const __half* Bg = WT + ((size_t)gate * Hsz + h0) * K;
    const int tid = threadIdx.x, lane = tid & 31, wid = tid >> 5;
    const int gid = lane >> 2, tig = lane & 3;
    const int wm0 = (wid & 1) * 64, wn0 = (wid >> 1) * 32;
    const int l7 = lane & 7, l8 = (lane >> 3) & 1, l16 = lane >> 4;

    uint32_t araw[4], braw[4];
    #pragma unroll
    for (int mt = 0; mt < 4; mt++)
        araw[mt] = (uint32_t)((wm0 + mt * 16 + l7 + l8 * 8) * 144 + l16 * 16);
    #pragma unroll
    for (int nt = 0; nt < 4; nt++)
        braw[nt] = (uint32_t)(18432 + (wn0 + nt * 8 + l7) * 144 + l8 * 16);

    auto stage = [&](int buf, int kk) {
        uint32_t base = sb + buf * GBUF;
        #pragma unroll
        for (int i = 0; i < 4; i++) {
            int idx = tid + i * 256; int r = idx >> 3, q = idx & 7;
            cp16(base + r * 144 + q * 16, A + (size_t)(m0 + r) * K + kk + q * 8);
        }
        #pragma unroll
        for (int i = 0; i < 4; i++) {
            int idx = tid + i * 256; int r = idx >> 3, q = idx & 7;
            cp16(base + 18432 + r * 144 + q * 16, Bg + (size_t)r * K + kk + q * 8);
        }
        CP_COMMIT();
    };

    const int NC = K / 64;
    stage(0, 0);
    if (NC > 1) stage(1, 64);
    float acc[16][4] = {};

    #pragma unroll 1
    for (int ch = 0; ch < NC; ch++) {
        if (ch + 2 < NC) {
            stage((ch + 2) % 3, (ch + 2) * 64);
            CP_WAIT(2);
        } else if (ch + 1 < NC) {
            CP_WAIT(1);
        } else {
            CP_WAIT(0);
        }
        __syncthreads();
        uint32_t bufb = sb + (ch % 3) * GBUF;
        #pragma unroll
        for (int s = 0; s < 4; s++) {
            uint32_t a[4][4], b[4][2];
            #pragma unroll
            for (int mt = 0; mt < 4; mt++) ldsm4(a[mt], bufb + araw[mt] + s * 32);
            #pragma unroll
            for (int nt = 0; nt < 4; nt++) ldsm2(b[nt], bufb + braw[nt] + s * 32);
            #pragma unroll
            for (int mt = 0; mt < 4; mt++)
                #pragma unroll
                for (int nt = 0; nt < 4; nt++)
                    mma16(acc[mt * 4 + nt], a[mt], b[nt]);
        }
        __syncthreads();
    }

    #pragma unroll
    for (int u = 0; u < 16; u++) {
        int mt = u >> 2, nt = u & 3;
        int row = m0 + wm0 + mt * 16 + gid;
        int col = n0 + wn0 + nt * 8 + tig * 2;
        float b0 = bias[col], b1 = bias[col + 1];
        *(__half2*)&Z[(size_t)row * NG + col] =
            __floats2half2_rn(acc[u][0] + b0, acc[u][1] + b1);
        *(__half2*)&Z[(size_t)(row + 8) * NG + col] =
            __floats2half2_rn(acc[u][2] + b0, acc[u][3] + b1);
    }
}

// ---------------- fused persistent 2-layer recurrence, split phase-barriers ----------------
// Grid (32, 4) = 128 CTAs, 256 threads, 257 epochs.
// bar1[grp]: arrivals after gates1 (h1s[e+1] published)  -> spin1 at epoch top (usually free)
// bar2[grp]: arrivals after gates2 (h2s[e] published)    -> spin2 mid-epoch (hidden by layer1)
__global__ void __launch_bounds__(256, 1)
lstm_fused(const __half* __restrict__ Zx1,   // [T, B, 4H] fp16
           const float* __restrict__ Wh1,    // [4, H, H] fp32
           const float* __restrict__ Wh2,    // [4, H, H] fp32
           __half* __restrict__ h1s,         // [(T+1), B, H], slot 0 zeroed
           __half* __restrict__ h2s,         // [(T+1), B, H], slot 0 zeroed
           unsigned* __restrict__ bar,       // [8]: bar1 = bar[grp], bar2 = bar[4+grp]
           const __half* __restrict__ W2T,   // [4, H, 512] fp16 (Wx2 transposed)
           const float* __restrict__ bias2)  // [4*H]
{
    extern __shared__ __align__(16) unsigned char smraw[];
    const uint32_t sb = smem_u32(smraw);
    __half* Wh2s = (__half*)smraw;                 // [64 n][520 halves]
    float*  zs0 = (float*)(smraw + OFF_Z0);
    __half* zs1 = (__half*)(smraw + OFF_Z1);

    const int h0 = blockIdx.x * 16;
    const int m0 = blockIdx.y * 64;
    const int tid = threadIdx.x, lane = tid & 31, wid = tid >> 5;
    const int gid = lane >> 2, tig = lane & 3;
    const int wm0 = (wid & 1) * 32, wn0 = ((wid >> 1) & 1) * 32;
    const int kh  = wid >> 2;
    const int l7 = lane & 7, l8 = (lane >> 3) & 1, l16 = lane >> 4;
    const unsigned grp = blockIdx.y;

    // ---- init 1: Wh1 slice -> A region (n-major fp16), ldsm into registers ----
    #pragma unroll 4
    for (int i = 0; i < 32; i++) {
        int f4 = tid + i * 256;
        int k = f4 >> 4, rem = f4 & 15, g = rem >> 2, q = rem & 3;
        float4 v = *(const float4*)(Wh1 + ((size_t)g * Hsz + k) * Hsz + h0 + q * 4);
        int nb = g * 16 + q * 4;
        __half* dst = (__half*)(smraw + OFF_AS);
        dst[(nb + 0) * 520 + k] = __float2half_rn(v.x);
        dst[(nb + 1) * 520 + k] = __float2half_rn(v.y);
        dst[(nb + 2) * 520 + k] = __float2half_rn(v.z);
        dst[(nb + 3) * 520 + k] = __float2half_rn(v.w);
    }
    __syncthreads();
    uint32_t breg[4][16][2];
    #pragma unroll
    for (int nt = 0; nt < 4; nt++) {
        uint32_t base = sb + OFF_AS + (wn0 + nt * 8 + l7) * 1040 + l8 * 16 + kh * 512;
        #pragma unroll
        for (int ks = 0; ks < 16; ks++)
            ldsm2(breg[nt][ks], base + ks * 32);
    }
    __syncthreads();

    // ---- init 2: Wh2 slice -> Wh2s (n-major fp16); Wx2 slice -> OFF_WX ----
    #pragma unroll 4
    for (int i = 0; i < 32; i++) {
        int f4 = tid + i * 256;
        int k = f4 >> 4, rem = f4 & 15, g = rem >> 2, q = rem & 3;
        float4 v = *(const float4*)(Wh2 + ((size_t)g * Hsz + k) * Hsz + h0 + q * 4);
        int nb = g * 16 + q * 4;
        Wh2s[(nb + 0) * 520 + k] = __float2half_rn(v.x);
        Wh2s[(nb + 1) * 520 + k] = __float2half_rn(v.y);
        Wh2s[(nb + 2) * 520 + k] = __float2half_rn(v.z);
        Wh2s[(nb + 3) * 520 + k] = __float2half_rn(v.w);
    }
    #pragma unroll
    for (int i = 0; i < 16; i++) {
        int idx = tid + i * 256;
        int n = idx >> 6, q = idx & 63;
        int g = n >> 4, hh = n & 15;
        cp16(sb + OFF_WX + n * 1040 + q * 16,
             W2T + ((size_t)g * Hsz + h0 + hh) * 512 + q * 8);
    }
    CP_COMMIT();
    CP_WAIT(0);
    __syncthreads();

    // t-invariant split-K fragment addresses
    uint32_t abase[2], bbase2[4], xbase[4];
    #pragma unroll
    for (int mt = 0; mt < 2; mt++)
        abase[mt] = sb + OFF_AS + (wm0 + mt * 16 + l7 + l8 * 8) * 1040 + l16 * 16 + kh * 512;
    #pragma unroll
    for (int nt = 0; nt < 4; nt++) {
        bbase2[nt] = sb + (wn0 + nt * 8 + l7) * 1040 + l8 * 16 + kh * 512;
        xbase[nt]  = sb + OFF_WX + (wn0 + nt * 8 + l7) * 1040 + l8 * 16 + kh * 512;
    }

    const int rr = tid >> 2;
    const int hq = (tid & 3) * 4;
    float cr1[4] = {0.f, 0.f, 0.f, 0.f};
    float cr2[4] = {0.f, 0.f, 0.f, 0.f};

    float b2a[4][4];
    #pragma unroll
    for (int g = 0; g < 4; g++)
        #pragma unroll
        for (int j = 0; j < 4; j++)
            b2a[g][j] = bias2[g * Hsz + h0 + hq + j];

    auto stageA_issue = [&](const __half* hp) {
        #pragma unroll
        for (int i = 0; i < 16; i++) {
            int f4 = tid + i * 256;
            int row = f4 >> 6, u = f4 & 63;
            cp16(sb + OFF_AS + row * 1040 + u * 16, hp + (size_t)row * Hsz + u * 8);
        }
        CP_COMMIT();
    };

    auto zstage = [&](float (*acc)[4]) {
        #pragma unroll
        for (int u = 0; u < 8; u++) {
            int mt = u >> 2, nt = u & 3;
            int row = wm0 + mt * 16 + gid, col = wn0 + nt * 8 + tig * 2;
            if (kh == 0) {
                *(float2*)&zs0[row * PZ + col]       = make_float2(acc[u][0], acc[u][1]);
                *(float2*)&zs0[(row + 8) * PZ + col] = make_float2(acc[u][2], acc[u][3]);
            } else {
                *(__half2*)&zs1[row * PZ1 + col]       = __floats2half2_rn(acc[u][0], acc[u][1]);
                *(__half2*)&zs1[(row + 8) * PZ1 + col] = __floats2half2_rn(acc[u][2], acc[u][3]);
            }
        }
    };

    auto gates = [&](const float (*zxa)[4], float* cr, __half* hout) {
        const float* z0 = &zs0[rr * PZ];
        const __half* z1 = &zs1[rr * PZ1];
        __half hv[4];
        #pragma unroll
        for (int j = 0; j < 4; j++) {
            float zg = z0[hq + j]      + __half2float(z1[hq + j])      + zxa[0][j];
            float zi = z0[16 + hq + j] + __half2float(z1[16 + hq + j]) + zxa[1][j];
            float zf = z0[32 + hq + j] + __half2float(z1[32 + hq + j]) + zxa[2][j];
            float zo = z0[48 + hq + j] + __half2float(z1[48 + hq + j]) + zxa[3][j];
            float gg = tanha(zg);
            float ii = sigf(zi);
            float ff = sigf(zf);
            float oo = sigf(zo);
            float cn = __fmaf_rn(gg, ii, cr[j] * ff);
            cr[j] = cn;
            hv[j] = __float2half_rn(tanha(cn) * oo);
        }
        *(uint2*)hout = *(uint2*)hv;
    };

    #pragma unroll 1
    for (int e = 0; e <= 256; e++) {
        const bool do1 = (e <= 255);   // layer1 step e
        const bool do2 = (e >= 1);     // layer2 step e-1

        // spin1: h1s[e] fully published (arrive1 happened mid-epoch e-1 -> usually free)
        if (e > 0) {
            if (tid == 0) bar_spin(&bar[grp], 32u * (unsigned)e);
            __syncthreads();
        }

        // stage h1s[e] -> A; prefetch Zx1[e] during cp.async flight
        stageA_issue(h1s + (size_t)e * (Bsz * Hsz) + (size_t)m0 * Hsz);
        float zxa1[4][4];
        if (do1) {
            const __half* zxp = Zx1 + (size_t)e * (Bsz * NG) + (size_t)(m0 + rr) * NG + h0 + hq;
            #pragma unroll
            for (int g = 0; g < 4; g++) {
                uint2 u = __ldcs((const uint2*)(zxp + g * Hsz));
                __half2* zh = (__half2*)&u;
                float2 lo = __half22float2(zh[0]);
                float2 hi = __half22float2(zh[1]);
                zxa1[g][0] = lo.x; zxa1[g][1] = lo.y; zxa1[g][2] = hi.x; zxa1[g][3] = hi.y;
            }
        }
        CP_WAIT(0);
        __syncthreads();

        // combined mma: A loaded once; layer1 uses breg, layer2 pass2 uses Wx2 frags
        float acc1[8][4] = {};
        float acc2[8][4] = {};
        #pragma unroll
        for (int ks = 0; ks < 16; ks++) {
            uint32_t a[2][4];
            ldsm4(a[0], abase[0] + ks * 32);
            ldsm4(a[1], abase[1] + ks * 32);
            if (do1) {
                #pragma unroll
                for (int mt = 0; mt < 2; mt++)
                    #pragma unroll
                    for (int nt = 0; nt < 4; nt++)
                        mma16(acc1[mt * 4 + nt], a[mt], breg[nt][ks]);
            }
            if (do2) {
                uint32_t b[4][2];
                #pragma unroll
                for (int nt = 0; nt < 4; nt++) ldsm2(b[nt], xbase[nt] + ks * 32);
                #pragma unroll
                for (int mt = 0; mt < 2; mt++)
                    #pragma unroll
                    for (int nt = 0; nt < 4; nt++)
                        mma16(acc2[mt * 4 + nt], a[mt], b[nt]);
            }
        }

        // layer1 finish: zstage, gates -> h1s[e+1], arrive1
        if (do1) {
            zstage(acc1);
            __syncthreads();
            gates(zxa1, cr1,
                  h1s + (size_t)(e + 1) * (Bsz * Hsz) + (size_t)(m0 + rr) * Hsz + h0 + hq);
        }
        __syncthreads();   // gates1 stores + all A/zs reads done

        if (tid == 0) {
            if (do1) bar_arrive(&bar[grp]);                        // h1s[e+1] published
            if (e >= 2) bar_spin(&bar[4 + grp], 32u * (unsigned)(e - 1));  // h2s[e-1] ready
        }
        __syncthreads();

        // layer2 step e-1: stage h2s[e-1], pass1 mma, gates -> h2s[e], arrive2
        if (do2) {
            stageA_issue(h2s + (size_t)(e - 1) * (Bsz * Hsz) + (size_t)m0 * Hsz);
            CP_WAIT(0);
            __syncthreads();

            #pragma unroll
            for (int ks = 0; ks < 16; ks++) {
                uint32_t a[2][4], b[4][2];
                ldsm4(a[0], abase[0] + ks * 32);
                ldsm4(a[1], abase[1] + ks * 32);
                #pragma unroll
                for (int nt = 0; nt < 4; nt++) ldsm2(b[nt], bbase2[nt] + ks * 32);
                #pragma unroll
                for (int mt = 0; mt < 2; mt++)
                    #pragma unroll
                    for (int nt = 0; nt < 4; nt++)
                        mma16(acc2[mt * 4 + nt], a[mt], b[nt]);
            }
            zstage(acc2);
            __syncthreads();
            gates(b2a, cr2,
                  h2s + (size_t)e * (Bsz * Hsz) + (size_t)(m0 + rr) * Hsz + h0 + hq);

            if (e <= 255) {
                __syncthreads();
                if (tid == 0) bar_arrive(&bar[4 + grp]);           // h2s[e] published
            }
        }
    }
}

// ---------------- final projection ----------------
__global__ void proj_kernel(const __half* __restrict__ h2,
                            const float* __restrict__ Wph,
                            const float* __restrict__ bp,
                            float* __restrict__ out) {
    int idx = blockIdx.x * blockDim.x + threadIdx.x;
    if (idx >= Bsz * Csz) return;
    int b = idx / Csz, cc = idx % Csz;
    float s = bp[cc];
    for (int k = 0; k < Hsz; k++)
        s += __half2float(h2[(size_t)b * Hsz + k]) * Wph[(size_t)k * Csz + cc];
    out[idx] = s;
}

// ---------------- launch ----------------
extern "C" void kernel_launch(void* const* d_in, const int* in_sizes, int n_in,
                              void* d_out, int out_size) {
    const float* x   = (const float*)d_in[0];
    const float* Wx1 = (const float*)d_in[1];
    const float* Wh1 = (const float*)d_in[2];
    const float* b1  = (const float*)d_in[3];
    const float* Wx2 = (const float*)d_in[4];
    const float* Wh2 = (const float*)d_in[5];
    const float* b2  = (const float*)d_in[6];
    const float* Wph = (const float*)d_in[7];
    const float* bp  = (const float*)d_in[8];
    float* out = (float*)d_out;

    __half *Zx1, *h1, *h2, *xT, *W1T, *W2T;
    unsigned* bar;
    cudaGetSymbolAddress((void**)&Zx1, g_Zx1);
    cudaGetSymbolAddress((void**)&h1,  g_h1);
    cudaGetSymbolAddress((void**)&h2,  g_h2);
    cudaGetSymbolAddress((void**)&xT,  g_xT);
    cudaGetSymbolAddress((void**)&W1T, g_W1T);
    cudaGetSymbolAddress((void**)&W2T, g_W2T);
    cudaGetSymbolAddress((void**)&bar, g_bar);

    cudaFuncSetAttribute(lstm_fused, cudaFuncAttributeMaxDynamicSharedMemorySize, PSM);
    cudaFuncSetAttribute(gemm_h2, cudaFuncAttributeMaxDynamicSharedMemorySize, GSM);

    init_kernel<<<(Bsz * Hsz + 255) / 256, 256>>>();

    prep_x<<<(Tt * Bsz * 16 + 255) / 256, 256>>>(x, xT);
    prep_w<<<(4 * Hsz * (Isz / 2) + 255) / 256, 256>>>(Wx1, W1T, Isz);
    prep_w<<<(4 * Hsz * (Hsz / 2) + 255) / 256, 256>>>(Wx2, W2T, Hsz);

    // Phase 1: Zx1 = x @ Wx1 + b1
    gemm_h2<<<dim3(NG / 128, (Tt * Bsz) / 128), 256, GSM>>>(xT, W1T, b1, Zx1, Isz);

    // Phase 2: fused 2-layer recurrence (257 epochs, split phase-barriers)
    lstm_fused<<<dim3(Hsz / 16, Bsz / 64), 256, PSM>>>(
        Zx1, Wh1, Wh2, h1, h2, bar, W2T, b2);

    // Phase 3: projection
    proj_kernel<<<(Bsz * Csz + 255) / 256, 256>>>(
        h2 + (size_t)Tt * Bsz * Hsz, Wph, bp, out);
}

// round 16
// speedup vs baseline: 1.0541x; 1.0541x over previous
#include <cuda_runtime.h>
#include <cuda_fp16.h>
#include <math.h>
#include <stdint.h>

#define Bsz 256
#define Tt  256
#define Isz 128
#define Hsz 512
#define Csz 10
#define NG  2048   // 4*H

// fused-kernel smem (bytes); pitch 1040B (== 16 mod 128 -> conflict-free ldsm)
#define PZ     68    // z0 pitch (floats)
#define PZ1    68    // z1 pitch (halves)
#define OFF_AS 66560                          // A buffer (after Wh2s 64*1040)
#define OFF_Z0 (OFF_AS + 66560)               // 133120
#define OFF_Z1 (OFF_Z0 + 64 * PZ * 4)         // 150528
#define OFF_WX (OFF_Z1 + 64 * PZ1 * 2)        // 159232
#define PSM    (OFF_WX + 66560)               // 225792

// gemm: 3 buffers, each A(128x144B) + B(128x144B)
#define GBUF 36864
#define GSM  (3 * GBUF)

// ---------------- scratch ----------------
__device__ __half g_Zx1[(size_t)Tt * Bsz * NG];
__device__ __half g_Zx2[(size_t)Tt * Bsz * NG];
__device__ __half g_h1[(size_t)(Tt + 1) * Bsz * Hsz];
__device__ __half g_h2[(size_t)(Tt + 1) * Bsz * Hsz];
__device__ __half g_xT[(size_t)Tt * Bsz * Isz];
__device__ __half g_W1T[(size_t)4 * Hsz * Isz];
__device__ __half g_W2T[(size_t)4 * Hsz * Hsz];
__device__ unsigned g_bar[8];

// ---------------- helpers ----------------
__device__ __forceinline__ void mma16(float* c, const uint32_t* a, const uint32_t* b) {
    asm volatile(
        "mma.sync.aligned.m16n8k16.row.col.f32.f16.f16.f32 "
        "{%0,%1,%2,%3},{%4,%5,%6,%7},{%8,%9},{%0,%1,%2,%3};"
        : "+f"(c[0]), "+f"(c[1]), "+f"(c[2]), "+f"(c[3])
        : "r"(a[0]), "r"(a[1]), "r"(a[2]), "r"(a[3]), "r"(b[0]), "r"(b[1]));
}
__device__ __forceinline__ void ldsm4(uint32_t* r, uint32_t addr) {
    asm volatile("ldmatrix.sync.aligned.m8n8.x4.shared.b16 {%0,%1,%2,%3}, [%4];"
        : "=r"(r[0]), "=r"(r[1]), "=r"(r[2]), "=r"(r[3]) : "r"(addr));
}
__device__ __forceinline__ void ldsm2(uint32_t* r, uint32_t addr) {
    asm volatile("ldmatrix.sync.aligned.m8n8.x2.shared.b16 {%0,%1}, [%2];"
        : "=r"(r[0]), "=r"(r[1]) : "r"(addr));
}
__device__ __forceinline__ float tanha(float x) {
    float y;
    asm("tanh.approx.f32 %0, %1;" : "=f"(y) : "f"(x));
    return y;
}
__device__ __forceinline__ float sigf(float x) {
    return __fmaf_rn(0.5f, tanha(0.5f * x), 0.5f);
}
__device__ __forceinline__ uint32_t smem_u32(const void* p) {
    uint32_t a;
    asm("{ .reg .u64 t; cvta.to.shared.u64 t, %1; cvt.u32.u64 %0, t; }" : "=r"(a) : "l"(p));
    return a;
}
__device__ __forceinline__ void cp16(uint32_t dst, const void* src) {
    asm volatile("cp.async.ca.shared.global [%0], [%1], 16;" :: "r"(dst), "l"(src));
}
#define CP_COMMIT() asm volatile("cp.async.commit_group;" ::: "memory")
#define CP_WAIT(n)  asm volatile("cp.async.wait_group %0;" :: "n"(n) : "memory")

__device__ __forceinline__ void bar_arrive(unsigned* p) {
    asm volatile("red.release.gpu.global.add.u32 [%0], %1;" :: "l"(p), "r"(1u) : "memory");
}
__device__ __forceinline__ void bar_spin(unsigned* p, unsigned tgt) {
    unsigned v;
    do {
        asm volatile("ld.acquire.gpu.global.u32 %0, [%1];" : "=r"(v) : "l"(p) : "memory");
    } while (v < tgt);
}

// ---------------- init ----------------
__global__ void init_kernel() {
    int i = blockIdx.x * blockDim.x + threadIdx.x;
    if (i < Bsz * Hsz) {
        g_h1[i] = __float2half(0.f);
        g_h2[i] = __float2half(0.f);
    }
    if (i < 8) g_bar[i] = 0u;
}

// ---------------- prep: x [b][t][k] fp32 -> xT [t][b][k] fp16 ----------------
__global__ void prep_x(const float* __restrict__ x, __half* __restrict__ xT) {
    int idx = blockIdx.x * blockDim.x + threadIdx.x;
    if (idx >= Tt * Bsz * 16) return;
    int q = idx & 15;
    int b = (idx >> 4) & (Bsz - 1);
    int t = idx >> 12;
    const float* src = x + ((size_t)b * Tt + t) * Isz + q * 8;
    float4 v0 = *(const float4*)src;
    float4 v1 = *(const float4*)(src + 4);
    __half2 h0 = __floats2half2_rn(v0.x, v0.y);
    __half2 h1 = __floats2half2_rn(v0.z, v0.w);
    __half2 h2 = __floats2half2_rn(v1.x, v1.y);
    __half2 h3 = __floats2half2_rn(v1.z, v1.w);
    uint4 u;
    u.x = *(uint32_t*)&h0; u.y = *(uint32_t*)&h1;
    u.z = *(uint32_t*)&h2; u.w = *(uint32_t*)&h3;
    *(uint4*)(xT + ((size_t)t * Bsz + b) * Isz + q * 8) = u;
}

// ---------------- prep: W[g][k][h] fp32 -> WT[g][h][k] fp16 ----------------
__global__ void prep_w(const float* __restrict__ W, __half* __restrict__ WT, int K) {
    int idx = blockIdx.x * blockDim.x + threadIdx.x;
    int kp = idx % (K / 2);
    int rest = idx / (K / 2);
    int h = rest % Hsz, g = rest / Hsz;
    if (g >= 4) return;
    int k = kp * 2;
    float a = W[((size_t)g * K + k) * Hsz + h];
    float b = W[((size_t)g * K + k + 1) * Hsz + h];
    *(__half2*)(WT + ((size_t)g * Hsz + h) * K + k) = __floats2half2_rn(a, b);
}

// ---------------- big GEMM (phase 1): fp16 in/out, cp.async 3-stage, 128x128 tile ----------------
__global__ void __launch_bounds__(256)
gemm_h2(const __half* __restrict__ A,
        const __half* __restrict__ WT,
        const float* __restrict__ bias,
        __half* __restrict__ Z,
        int K) {
    extern __shared__ __align__(16) unsigned char smg[];
    const uint32_t sb = smem_u32(smg);

    const int m0 = blockIdx.y * 128, n0 = blockIdx.x * 128;
    const int gate = n0 >> 9, h0 = n0 & 511;
    const __half* Bg = WT + ((size_t)gate * Hsz + h0) * K;
    const int tid = threadIdx.x, lane = tid & 31, wid = tid >> 5;
    const int gid = lane >> 2, tig = lane & 3;
    const int wm0 = (wid & 1) * 64, wn0 = (wid >> 1) * 32;
    const int l7 = lane & 7, l8 = (lane >> 3) & 1, l16 = lane >> 4;

    uint32_t araw[4], braw[4];
    #pragma unroll
    for (int mt = 0; mt < 4; mt++)
        araw[mt] = (uint32_t)((wm0 + mt * 16 + l7 + l8 * 8) * 144 + l16 * 16);
    #pragma unroll
    for (int nt = 0; nt < 4; nt++)
        braw[nt] = (uint32_t)(18432 + (wn0 + nt * 8 + l7) * 144 + l8 * 16);

    auto stage = [&](int buf, int kk) {
        uint32_t base = sb + buf * GBUF;
        #pragma unroll
        for (int i = 0; i < 4; i++) {
            int idx = tid + i * 256; int r = idx >> 3, q = idx & 7;
            cp16(base + r * 144 + q * 16, A + (size_t)(m0 + r) * K + kk + q * 8);
        }
        #pragma unroll
        for (int i = 0; i < 4; i++) {
            int idx = tid + i * 256; int r = idx >> 3, q = idx & 7;
            cp16(base + 18432 + r * 144 + q * 16, Bg + (size_t)r * K + kk + q * 8);
        }
        CP_COMMIT();
    };

    const int NC = K / 64;
    stage(0, 0);
    if (NC > 1) stage(1, 64);
    float acc[16][4] = {};

    #pragma unroll 1
    for (int ch = 0; ch < NC; ch++) {
        if (ch + 2 < NC) {
            stage((ch + 2) % 3, (ch + 2) * 64);
            CP_WAIT(2);
        } else if (ch + 1 < NC) {
            CP_WAIT(1);
        } else {
            CP_WAIT(0);
        }
        __syncthreads();
        uint32_t bufb = sb + (ch % 3) * GBUF;
        #pragma unroll
        for (int s = 0; s < 4; s++) {
            uint32_t a[4][4], b[4][2];
            #pragma unroll
            for (int mt = 0; mt < 4; mt++) ldsm4(a[mt], bufb + araw[mt] + s * 32);
            #pragma unroll
            for (int nt = 0; nt < 4; nt++) ldsm2(b[nt], bufb + braw[nt] + s * 32);
            #pragma unroll
            for (int mt = 0; mt < 4; mt++)
                #pragma unroll
                for (int nt = 0; nt < 4; nt++)
                    mma16(acc[mt * 4 + nt], a[mt], b[nt]);
        }
        __syncthreads();
    }

    #pragma unroll
    for (int u = 0; u < 16; u++) {
        int mt = u >> 2, nt = u & 3;
        int row = m0 + wm0 + mt * 16 + gid;
        int col = n0 + wn0 + nt * 8 + tig * 2;
        float b0 = bias[col], b1 = bias[col + 1];
        *(__half2*)&Z[(size_t)row * NG + col] =
            __floats2half2_rn(acc[u][0] + b0, acc[u][1] + b1);
        *(__half2*)&Z[(size_t)(row + 8) * NG + col] =
            __floats2half2_rn(acc[u][2] + b0, acc[u][3] + b1);
    }
}

// ---------------- fused persistent 2-layer recurrence (R12 structure, overlapped waits) ----------------
// Grid (32, 4) = 128 CTAs, 256 threads, 1 barrier per epoch, 258 epochs.
// Epoch e: layer1 step e (e<=255), produce Zx2(e-1) (1<=e<=256), layer2 step e-2 (e>=2).
// cp.async waits are overlapped: Zx1 prefetch rides the h1-stage flight; producer stores
// and Zx2 prefetch ride the h2-stage flight.
__global__ void __launch_bounds__(256, 1)
lstm_fused(const __half* __restrict__ Zx1,   // [T, B, 4H] fp16
           const float* __restrict__ Wh1,    // [4, H, H] fp32
           const float* __restrict__ Wh2,    // [4, H, H] fp32
           __half* __restrict__ h1s,         // [(T+1), B, H], slot 0 zeroed
           __half* __restrict__ h2s,         // [(T+1), B, H], slot 0 zeroed
           unsigned* __restrict__ bar,
           const __half* __restrict__ W2T,   // [4, H, 512] fp16
           const float* __restrict__ bias2,  // [4*H]
           __half* __restrict__ Zx2) {       // [T, B, 4H] fp16
    extern __shared__ __align__(16) unsigned char smraw[];
    const uint32_t sb = smem_u32(smraw);
    __half* Wh2s = (__half*)smraw;                 // [64 n][520 halves]
    float*  zs0 = (float*)(smraw + OFF_Z0);
    __half* zs1 = (__half*)(smraw + OFF_Z1);

    const int h0 = blockIdx.x * 16;
    const int m0 = blockIdx.y * 64;
    const int tid = threadIdx.x, lane = tid & 31, wid = tid >> 5;
    const int gid = lane >> 2, tig = lane & 3;
    const int wm0 = (wid & 1) * 32, wn0 = ((wid >> 1) & 1) * 32;
    const int kh  = wid >> 2;
    const int l7 = lane & 7, l8 = (lane >> 3) & 1, l16 = lane >> 4;
    const unsigned grp = blockIdx.y;

    // ---- init 1: Wh1 slice -> A region (n-major fp16), ldsm into registers ----
    #pragma unroll 4
    for (int i = 0; i < 32; i++) {
        int f4 = tid + i * 256;
        int k = f4 >> 4, rem = f4 & 15, g = rem >> 2, q = rem & 3;
        float4 v = *(const float4*)(Wh1 + ((size_t)g * Hsz + k) * Hsz + h0 + q * 4);
        int nb = g * 16 + q * 4;
        __half* dst = (__half*)(smraw + OFF_AS);
        dst[(nb + 0) * 520 + k] = __float2half_rn(v.x);
        dst[(nb + 1) * 520 + k] = __float2half_rn(v.y);
        dst[(nb + 2) * 520 + k] = __float2half_rn(v.z);
        dst[(nb + 3) * 520 + k] = __float2half_rn(v.w);
    }
    __syncthreads();
    uint32_t breg[4][16][2];
    #pragma unroll
    for (int nt = 0; nt < 4; nt++) {
        uint32_t base = sb + OFF_AS + (wn0 + nt * 8 + l7) * 1040 + l8 * 16 + kh * 512;
        #pragma unroll
        for (int ks = 0; ks < 16; ks++)
            ldsm2(breg[nt][ks], base + ks * 32);
    }
    __syncthreads();

    // ---- init 2: Wh2 slice -> Wh2s (n-major fp16); Wx2 slice -> OFF_WX ----
    #pragma unroll 4
    for (int i = 0; i < 32; i++) {
        int f4 = tid + i * 256;
        int k = f4 >> 4, rem = f4 & 15, g = rem >> 2, q = rem & 3;
        float4 v = *(const float4*)(Wh2 + ((size_t)g * Hsz + k) * Hsz + h0 + q * 4);
        int nb = g * 16 + q * 4;
        Wh2s[(nb + 0) * 520 + k] = __float2half_rn(v.x);
        Wh2s[(nb + 1) * 520 + k] = __float2half_rn(v.y);
        Wh2s[(nb + 2) * 520 + k] = __float2half_rn(v.z);
        Wh2s[(nb + 3) * 520 + k] = __float2half_rn(v.w);
    }
    #pragma unroll
    for (int i = 0; i < 16; i++) {
        int idx = tid + i * 256;
        int n = idx >> 6, q = idx & 63;
        int g = n >> 4, hh = n & 15;
        cp16(sb + OFF_WX + n * 1040 + q * 16,
             W2T + ((size_t)g * Hsz + h0 + hh) * 512 + q * 8);
    }
    CP_COMMIT();
    CP_WAIT(0);
    __syncthreads();

    // t-invariant fragment addresses
    uint32_t abase[2], bbase2[4];
    #pragma unroll
    for (int mt = 0; mt < 2; mt++)
        abase[mt] = sb + OFF_AS + (wm0 + mt * 16 + l7 + l8 * 8) * 1040 + l16 * 16 + kh * 512;
    #pragma unroll
    for (int nt = 0; nt < 4; nt++)
        bbase2[nt] = sb + (wn0 + nt * 8 + l7) * 1040 + l8 * 16 + kh * 512;

    // producer: full-K tiling
    const int wn0p = (wid >> 1) * 16;
    uint32_t pabase[2], pxbase[2];
    int gc2[2];
    float2 bsv2[2];
    #pragma unroll
    for (int mt = 0; mt < 2; mt++)
        pabase[mt] = sb + OFF_AS + (wm0 + mt * 16 + l7 + l8 * 8) * 1040 + l16 * 16;
    #pragma unroll
    for (int nt = 0; nt < 2; nt++) {
        pxbase[nt] = sb + OFF_WX + (wn0p + nt * 8 + l7) * 1040 + l8 * 16;
        int n = wn0p + nt * 8 + tig * 2;
        int g = n >> 4, hh = n & 15;
        gc2[nt] = g * Hsz + h0 + hh;
        bsv2[nt] = make_float2(bias2[gc2[nt]], bias2[gc2[nt] + 1]);
    }

    const int rr = tid >> 2;
    const int hq = (tid & 3) * 4;
    float cr1[4] = {0.f, 0.f, 0.f, 0.f};
    float cr2[4] = {0.f, 0.f, 0.f, 0.f};

    auto stageA_issue = [&](const __half* hp) {
        #pragma unroll
        for (int i = 0; i < 16; i++) {
            int f4 = tid + i * 256;
            int row = f4 >> 6, u = f4 & 63;
            cp16(sb + OFF_AS + row * 1040 + u * 16, hp + (size_t)row * Hsz + u * 8);
        }
        CP_COMMIT();
    };

    auto zstage = [&](float (*acc)[4]) {
        #pragma unroll
        for (int u = 0; u < 8; u++) {
            int mt = u >> 2, nt = u & 3;
            int row = wm0 + mt * 16 + gid, col = wn0 + nt * 8 + tig * 2;
            if (kh == 0) {
                *(float2*)&zs0[row * PZ + col]       = make_float2(acc[u][0], acc[u][1]);
                *(float2*)&zs0[(row + 8) * PZ + col] = make_float2(acc[u][2], acc[u][3]);
            } else {
                *(__half2*)&zs1[row * PZ1 + col]       = __floats2half2_rn(acc[u][0], acc[u][1]);
                *(__half2*)&zs1[(row + 8) * PZ1 + col] = __floats2half2_rn(acc[u][2], acc[u][3]);
            }
        }
    };

    // gates on zs + zxu -> cr + fp16 out
    auto gates = [&](uint2* zxu, float* cr, __half* hout) {
        const float* z0 = &zs0[rr * PZ];
        const __half* z1 = &zs1[rr * PZ1];
        float zxa[4][4];
        #pragma unroll
        for (int g = 0; g < 4; g++) {
            __half2* zh = (__half2*)&zxu[g];
            float2 lo = __half22float2(zh[0]);
            float2 hi = __half22float2(zh[1]);
            zxa[g][0] = lo.x; zxa[g][1] = lo.y; zxa[g][2] = hi.x; zxa[g][3] = hi.y;
        }
        __half hv[4];
        #pragma unroll
        for (int j = 0; j < 4; j++) {
            float zg = z0[hq + j]      + __half2float(z1[hq + j])      + zxa[0][j];
            float zi = z0[16 + hq + j] + __half2float(z1[16 + hq + j]) + zxa[1][j];
            float zf = z0[32 + hq + j] + __half2float(z1[32 + hq + j]) + zxa[2][j];
            float zo = z0[48 + hq + j] + __half2float(z1[48 + hq + j]) + zxa[3][j];
            float gg = tanha(zg);
            float ii = sigf(zi);
            float ff = sigf(zf);
            float oo = sigf(zo);
            float cn = __fmaf_rn(gg, ii, cr[j] * ff);
            cr[j] = cn;
            hv[j] = __float2half_rn(tanha(cn) * oo);
        }
        *(uint2*)hout = *(uint2*)hv;
    };

    #pragma unroll 1
    for (int e = 0; e <= 257; e++) {
        if (e > 0) {
            if (tid == 0) bar_spin(&bar[grp], 32u * (unsigned)e);
            __syncthreads();
        }

        const bool do1 = (e <= 255);
        const bool dop = (e >= 1 && e <= 256);
        const bool do2 = (e >= 2);

        // stage A <- h1(e); Zx1 prefetch rides the cp.async flight
        uint2 zxu1[4];
        if (e <= 256) {
            stageA_issue(h1s + (size_t)e * (Bsz * Hsz) + (size_t)m0 * Hsz);
            if (do1) {
                const __half* zxp = Zx1 + (size_t)e * (Bsz * NG) + (size_t)(m0 + rr) * NG + h0 + hq;
                #pragma unroll
                for (int g = 0; g < 4; g++) zxu1[g] = __ldcs((const uint2*)(zxp + g * Hsz));
            }
            CP_WAIT(0);
            __syncthreads();
        }

        // layer 1 step e
        if (do1) {
            float acc[8][4] = {};
            #pragma unroll
            for (int ks = 0; ks < 16; ks++) {
                uint32_t a[2][4];
                ldsm4(a[0], abase[0] + ks * 32);
                ldsm4(a[1], abase[1] + ks * 32);
                #pragma unroll
                for (int mt = 0; mt < 2; mt++)
                    #pragma unroll
                    for (int nt = 0; nt < 4; nt++)
                        mma16(acc[mt * 4 + nt], a[mt], breg[nt][ks]);
            }
            zstage(acc);
            __syncthreads();
            gates(zxu1, cr1,
                  h1s + (size_t)(e + 1) * (Bsz * Hsz) + (size_t)(m0 + rr) * Hsz + h0 + hq);
        }

        // producer mma: Zx2(e-1) from staged h1(e) (za stays in registers)
        float za[4][4] = {};
        if (dop) {
            #pragma unroll 8
            for (int ks = 0; ks < 32; ks++) {
                uint32_t a[2][4], b[2][2];
                ldsm4(a[0], pabase[0] + ks * 32);
                ldsm4(a[1], pabase[1] + ks * 32);
                ldsm2(b[0], pxbase[0] + ks * 32);
                ldsm2(b[1], pxbase[1] + ks * 32);
                mma16(za[0], a[0], b[0]); mma16(za[1], a[0], b[1]);
                mma16(za[2], a[1], b[0]); mma16(za[3], a[1], b[1]);
            }
        }
        __syncthreads();   // all A/zs reads retired

        // issue h2 stage first; producer stores + Zx2 prefetch ride the flight
        uint2 zxu2[4];
        if (do2)
            stageA_issue(h2s + (size_t)(e - 2) * (Bsz * Hsz) + (size_t)m0 * Hsz);
        if (dop) {
            __half* zb = Zx2 + ((size_t)(e - 1) * Bsz + m0) * NG;
            #pragma unroll
            for (int u = 0; u < 4; u++) {
                int mt = u >> 1, nt = u & 1;
                int row = wm0 + mt * 16 + gid;
                *(__half2*)&zb[(size_t)row * NG + gc2[nt]] =
                    __floats2half2_rn(za[u][0] + bsv2[nt].x, za[u][1] + bsv2[nt].y);
                *(__half2*)&zb[(size_t)(row + 8) * NG + gc2[nt]] =
                    __floats2half2_rn(za[u][2] + bsv2[nt].x, za[u][3] + bsv2[nt].y);
            }
        }
        if (do2) {
            const __half* zxp = Zx2 + (size_t)(e - 2) * (Bsz * NG) + (size_t)(m0 + rr) * NG + h0 + hq;
            #pragma unroll
            for (int g = 0; g < 4; g++) zxu2[g] = __ldcg((const uint2*)(zxp + g * Hsz));
            CP_WAIT(0);
            __syncthreads();

            float acc[8][4] = {};
            #pragma unroll
            for (int ks = 0; ks < 16; ks++) {
                uint32_t a[2][4], b[4][2];
                ldsm4(a[0], abase[0] + ks * 32);
                ldsm4(a[1], abase[1] + ks * 32);
                #pragma unroll
                for (int nt = 0; nt < 4; nt++) ldsm2(b[nt], bbase2[nt] + ks * 32);
                #pragma unroll
                for (int mt = 0; mt < 2; mt++)
                    #pragma unroll
                    for (int nt = 0; nt < 4; nt++)
                        mma16(acc[mt * 4 + nt], a[mt], b[nt]);
            }
            zstage(acc);
            __syncthreads();
            gates(zxu2, cr2,
                  h2s + (size_t)(e - 1) * (Bsz * Hsz) + (size_t)(m0 + rr) * Hsz + h0 + hq);
        }

        if (e < 257) {
            __syncthreads();
            if (tid == 0) bar_arrive(&bar[grp]);
        }
    }
}

// ---------------- final projection ----------------
__global__ void proj_kernel(const __half* __restrict__ h2,
                            const float* __restrict__ Wph,
                            const float* __restrict__ bp,
                            float* __restrict__ out) {
    int idx = blockIdx.x * blockDim.x + threadIdx.x;
    if (idx >= Bsz * Csz) return;
    int b = idx / Csz, cc = idx % Csz;
    float s = bp[cc];
    for (int k = 0; k < Hsz; k++)
        s += __half2float(h2[(size_t)b * Hsz + k]) * Wph[(size_t)k * Csz + cc];
    out[idx] = s;
}

// ---------------- launch ----------------
extern "C" void kernel_launch(void* const* d_in, const int* in_sizes, int n_in,
                              void* d_out, int out_size) {
    const float* x   = (const float*)d_in[0];
    const float* Wx1 = (const float*)d_in[1];
    const float* Wh1 = (const float*)d_in[2];
    const float* b1  = (const float*)d_in[3];
    const float* Wx2 = (const float*)d_in[4];
    const float* Wh2 = (const float*)d_in[5];
    const float* b2  = (const float*)d_in[6];
    const float* Wph = (const float*)d_in[7];
    const float* bp  = (const float*)d_in[8];
    float* out = (float*)d_out;

    __half *Zx1, *Zx2, *h1, *h2, *xT, *W1T, *W2T;
    unsigned* bar;
    cudaGetSymbolAddress((void**)&Zx1, g_Zx1);
    cudaGetSymbolAddress((void**)&Zx2, g_Zx2);
    cudaGetSymbolAddress((void**)&h1,  g_h1);
    cudaGetSymbolAddress((void**)&h2,  g_h2);
    cudaGetSymbolAddress((void**)&xT,  g_xT);
    cudaGetSymbolAddress((void**)&W1T, g_W1T);
    cudaGetSymbolAddress((void**)&W2T, g_W2T);
    cudaGetSymbolAddress((void**)&bar, g_bar);

    cudaFuncSetAttribute(lstm_fused, cudaFuncAttributeMaxDynamicSharedMemorySize, PSM);
    cudaFuncSetAttribute(gemm_h2, cudaFuncAttributeMaxDynamicSharedMemorySize, GSM);

    init_kernel<<<(Bsz * Hsz + 255) / 256, 256>>>();

    prep_x<<<(Tt * Bsz * 16 + 255) / 256, 256>>>(x, xT);
    prep_w<<<(4 * Hsz * (Isz / 2) + 255) / 256, 256>>>(Wx1, W1T, Isz);
    prep_w<<<(4 * Hsz * (Hsz / 2) + 255) / 256, 256>>>(Wx2, W2T, Hsz);

    // Phase 1: Zx1 = x @ Wx1 + b1
    gemm_h2<<<dim3(NG / 128, (Tt * Bsz) / 128), 256, GSM>>>(xT, W1T, b1, Zx1, Isz);

    // Phase 2: fused 2-layer recurrence (258 epochs, 1 barrier each, overlapped waits)
    lstm_fused<<<dim3(Hsz / 16, Bsz / 64), 256, PSM>>>(
        Zx1, Wh1, Wh2, h1, h2, bar, W2T, b2, Zx2);

    // Phase 3: projection
    proj_kernel<<<(Bsz * Csz + 255) / 256, 256>>>(
        h2 + (size_t)Tt * Bsz * Hsz, Wph, bp, out);
}

// round 17
// speedup vs baseline: 1.0872x; 1.0314x over previous
#include <cuda_runtime.h>
#include <cuda_fp16.h>
#include <math.h>
#include <stdint.h>

#define Bsz 256
#define Tt  256
#define Isz 128
#define Hsz 512
#define Csz 10
#define NG  2048   // 4*H

// fused-kernel smem (bytes); pitch 1040B (== 16 mod 128 -> conflict-free ldsm)
#define PZ     68    // z0 pitch (floats)
#define PZ1    68    // z1 pitch (halves)
#define OFF_AS 66560                          // A buffer (after Wh2s 64*1040)
#define OFF_Z0 (OFF_AS + 66560)               // 133120
#define OFF_Z1 (OFF_Z0 + 64 * PZ * 4)         // 150528
#define OFF_WX (OFF_Z1 + 64 * PZ1 * 2)        // 159232
#define PSM    (OFF_WX + 66560)               // 225792

// gemm: 3 buffers, each A(128x144B) + B(128x144B)
#define GBUF 36864
#define GSM  (3 * GBUF)

// ---------------- scratch ----------------
__device__ __half g_Zx1[(size_t)Tt * Bsz * NG];
__device__ __half g_Zx2[(size_t)Tt * Bsz * NG];
__device__ __half g_h1[(size_t)(Tt + 1) * Bsz * Hsz];
__device__ __half g_h2[(size_t)(Tt + 1) * Bsz * Hsz];
__device__ __half g_xT[(size_t)Tt * Bsz * Isz];
__device__ __half g_W1T[(size_t)4 * Hsz * Isz];
__device__ __half g_W2T[(size_t)4 * Hsz * Hsz];
__device__ unsigned g_bar[8];

// ---------------- helpers ----------------
__device__ __forceinline__ void mma16(float* c, const uint32_t* a, const uint32_t* b) {
    asm volatile(
        "mma.sync.aligned.m16n8k16.row.col.f32.f16.f16.f32 "
        "{%0,%1,%2,%3},{%4,%5,%6,%7},{%8,%9},{%0,%1,%2,%3};"
        : "+f"(c[0]), "+f"(c[1]), "+f"(c[2]), "+f"(c[3])
        : "r"(a[0]), "r"(a[1]), "r"(a[2]), "r"(a[3]), "r"(b[0]), "r"(b[1]));
}
__device__ __forceinline__ void ldsm4(uint32_t* r, uint32_t addr) {
    asm volatile("ldmatrix.sync.aligned.m8n8.x4.shared.b16 {%0,%1,%2,%3}, [%4];"
        : "=r"(r[0]), "=r"(r[1]), "=r"(r[2]), "=r"(r[3]) : "r"(addr));
}
__device__ __forceinline__ void ldsm2(uint32_t* r, uint32_t addr) {
    asm volatile("ldmatrix.sync.aligned.m8n8.x2.shared.b16 {%0,%1}, [%2];"
        : "=r"(r[0]), "=r"(r[1]) : "r"(addr));
}
__device__ __forceinline__ float tanha(float x) {
    float y;
    asm("tanh.approx.f32 %0, %1;" : "=f"(y) : "f"(x));
    return y;
}
__device__ __forceinline__ float sigf(float x) {
    return __fmaf_rn(0.5f, tanha(0.5f * x), 0.5f);
}
__device__ __forceinline__ uint32_t smem_u32(const void* p) {
    uint32_t a;
    asm("{ .reg .u64 t; cvta.to.shared.u64 t, %1; cvt.u32.u64 %0, t; }" : "=r"(a) : "l"(p));
    return a;
}
__device__ __forceinline__ void cp16(uint32_t dst, const void* src) {
    asm volatile("cp.async.ca.shared.global [%0], [%1], 16;" :: "r"(dst), "l"(src));
}
#define CP_COMMIT() asm volatile("cp.async.commit_group;" ::: "memory")
#define CP_WAIT(n)  asm volatile("cp.async.wait_group %0;" :: "n"(n) : "memory")

__device__ __forceinline__ void bar_arrive(unsigned* p) {
    asm volatile("red.release.gpu.global.add.u32 [%0], %1;" :: "l"(p), "r"(1u) : "memory");
}
__device__ __forceinline__ void bar_spin(unsigned* p, unsigned tgt) {
    unsigned v;
    do {
        asm volatile("ld.acquire.gpu.global.u32 %0, [%1];" : "=r"(v) : "l"(p) : "memory");
    } while (v < tgt);
}

// ---------------- init ----------------
__global__ void init_kernel() {
    int i = blockIdx.x * blockDim.x + threadIdx.x;
    if (i < Bsz * Hsz) {
        g_h1[i] = __float2half(0.f);
        g_h2[i] = __float2half(0.f);
    }
    if (i < 8) g_bar[i] = 0u;
}

// ---------------- prep: x [b][t][k] fp32 -> xT [t][b][k] fp16 ----------------
__global__ void prep_x(const float* __restrict__ x, __half* __restrict__ xT) {
    int idx = blockIdx.x * blockDim.x + threadIdx.x;
    if (idx >= Tt * Bsz * 16) return;
    int q = idx & 15;
    int b = (idx >> 4) & (Bsz - 1);
    int t = idx >> 12;
    const float* src = x + ((size_t)b * Tt + t) * Isz + q * 8;
    float4 v0 = *(const float4*)src;
    float4 v1 = *(const float4*)(src + 4);
    __half2 h0 = __floats2half2_rn(v0.x, v0.y);
    __half2 h1 = __floats2half2_rn(v0.z, v0.w);
    __half2 h2 = __floats2half2_rn(v1.x, v1.y);
    __half2 h3 = __floats2half2_rn(v1.z, v1.w);
    uint4 u;
    u.x = *(uint32_t*)&h0; u.y = *(uint32_t*)&h1;
    u.z = *(uint32_t*)&h2; u.w = *(uint32_t*)&h3;
    *(uint4*)(xT + ((size_t)t * Bsz + b) * Isz + q * 8) = u;
}

// ---------------- prep: W[g][k][h] fp32 -> WT[g][h][k] fp16 ----------------
__global__ void prep_w(const float* __restrict__ W, __half* __restrict__ WT, int K) {
    int idx = blockIdx.x * blockDim.x + threadIdx.x;
    int kp = idx % (K / 2);
    int rest = idx / (K / 2);
    int h = rest % Hsz, g = rest / Hsz;
    if (g >= 4) return;
    int k = kp * 2;
    float a = W[((size_t)g * K + k) * Hsz + h];
    float b = W[((size_t)g * K + k + 1) * Hsz + h];
    *(__half2*)(WT + ((size_t)g * Hsz + h) * K + k) = __floats2half2_rn(a, b);
}

// ---------------- big GEMM (phase 1): fp16 in/out, cp.async 3-stage, 128x128 tile ----------------
__global__ void __launch_bounds__(256)
gemm_h2(const __half* __restrict__ A,
        const __half* __restrict__ WT,
        const float* __restrict__ bias,
        __half* __restrict__ Z,
        int K) {
    extern __shared__ __align__(16) unsigned char smg[];
    const uint32_t sb = smem_u32(smg);

    const int m0 = blockIdx.y * 128, n0 = blockIdx.x * 128;
    const int gate = n0 >> 9, h0 = n0 & 511;
    const __half* Bg = WT + ((size_t)gate * Hsz + h0) * K;
    const int tid = threadIdx.x, lane = tid & 31, wid = tid >> 5;
    const int gid = lane >> 2, tig = lane & 3;
    const int wm0 = (wid & 1) * 64, wn0 = (wid >> 1) * 32;
    const int l7 = lane & 7, l8 = (lane >> 3) & 1, l16 = lane >> 4;

    uint32_t araw[4], braw[4];
    #pragma unroll
    for (int mt = 0; mt < 4; mt++)
        araw[mt] = (uint32_t)((wm0 + mt * 16 + l7 + l8 * 8) * 144 + l16 * 16);
    #pragma unroll
    for (int nt = 0; nt < 4; nt++)
        braw[nt] = (uint32_t)(18432 + (wn0 + nt * 8 + l7) * 144 + l8 * 16);

    auto stage = [&](int buf, int kk) {
        uint32_t base = sb + buf * GBUF;
        #pragma unroll
        for (int i = 0; i < 4; i++) {
            int idx = tid + i * 256; int r = idx >> 3, q = idx & 7;
            cp16(base + r * 144 + q * 16, A + (size_t)(m0 + r) * K + kk + q * 8);
        }
        #pragma unroll
        for (int i = 0; i < 4; i++) {
            int idx = tid + i * 256; int r = idx >> 3, q = idx & 7;
            cp16(base + 18432 + r * 144 + q * 16, Bg + (size_t)r * K + kk + q * 8);
        }
        CP_COMMIT();
    };

    const int NC = K / 64;
    stage(0, 0);
    if (NC > 1) stage(1, 64);
    float acc[16][4] = {};

    #pragma unroll 1
    for (int ch = 0; ch < NC; ch++) {
        if (ch + 2 < NC) {
            stage((ch + 2) % 3, (ch + 2) * 64);
            CP_WAIT(2);
        } else if (ch + 1 < NC) {
            CP_WAIT(1);
        } else {
            CP_WAIT(0);
        }
        __syncthreads();
        uint32_t bufb = sb + (ch % 3) * GBUF;
        #pragma unroll
        for (int s = 0; s < 4; s++) {
            uint32_t a[4][4], b[4][2];
            #pragma unroll
            for (int mt = 0; mt < 4; mt++) ldsm4(a[mt], bufb + araw[mt] + s * 32);
            #pragma unroll
            for (int nt = 0; nt < 4; nt++) ldsm2(b[nt], bufb + braw[nt] + s * 32);
            #pragma unroll
            for (int mt = 0; mt < 4; mt++)
                #pragma unroll
                for (int nt = 0; nt < 4; nt++)
                    mma16(acc[mt * 4 + nt], a[mt], b[nt]);
        }
        __syncthreads();
    }

    #pragma unroll
    for (int u = 0; u < 16; u++) {
        int mt = u >> 2, nt = u & 3;
        int row = m0 + wm0 + mt * 16 + gid;
        int col = n0 + wn0 + nt * 8 + tig * 2;
        float b0 = bias[col], b1 = bias[col + 1];
        *(__half2*)&Z[(size_t)row * NG + col] =
            __floats2half2_rn(acc[u][0] + b0, acc[u][1] + b1);
        *(__half2*)&Z[(size_t)(row + 8) * NG + col] =
            __floats2half2_rn(acc[u][2] + b0, acc[u][3] + b1);
    }
}

// ---------------- fused persistent 2-layer recurrence (R12 structure; prefetches ride cp.async flights) ----------------
// Grid (32, 4) = 128 CTAs, 256 threads, 1 barrier per epoch, 258 epochs.
// Epoch e: layer1 step e (e<=255), produce Zx2(e-1) (1<=e<=256), layer2 step e-2 (e>=2).
__global__ void __launch_bounds__(256, 1)
lstm_fused(const __half* __restrict__ Zx1,   // [T, B, 4H] fp16
           const float* __restrict__ Wh1,    // [4, H, H] fp32
           const float* __restrict__ Wh2,    // [4, H, H] fp32
           __half* __restrict__ h1s,         // [(T+1), B, H], slot 0 zeroed
           __half* __restrict__ h2s,         // [(T+1), B, H], slot 0 zeroed
           unsigned* __restrict__ bar,
           const __half* __restrict__ W2T,   // [4, H, 512] fp16
           const float* __restrict__ bias2,  // [4*H]
           __half* __restrict__ Zx2) {       // [T, B, 4H] fp16
    extern __shared__ __align__(16) unsigned char smraw[];
    const uint32_t sb = smem_u32(smraw);
    __half* Wh2s = (__half*)smraw;                 // [64 n][520 halves]
    float*  zs0 = (float*)(smraw + OFF_Z0);
    __half* zs1 = (__half*)(smraw + OFF_Z1);

    const int h0 = blockIdx.x * 16;
    const int m0 = blockIdx.y * 64;
    const int tid = threadIdx.x, lane = tid & 31, wid = tid >> 5;
    const int gid = lane >> 2, tig = lane & 3;
    const int wm0 = (wid & 1) * 32, wn0 = ((wid >> 1) & 1) * 32;
    const int kh  = wid >> 2;
    const int l7 = lane & 7, l8 = (lane >> 3) & 1, l16 = lane >> 4;
    const unsigned grp = blockIdx.y;

    // ---- init 1: Wh1 slice -> A region (n-major fp16), ldsm into registers ----
    #pragma unroll 4
    for (int i = 0; i < 32; i++) {
        int f4 = tid + i * 256;
        int k = f4 >> 4, rem = f4 & 15, g = rem >> 2, q = rem & 3;
        float4 v = *(const float4*)(Wh1 + ((size_t)g * Hsz + k) * Hsz + h0 + q * 4);
        int nb = g * 16 + q * 4;
        __half* dst = (__half*)(smraw + OFF_AS);
        dst[(nb + 0) * 520 + k] = __float2half_rn(v.x);
        dst[(nb + 1) * 520 + k] = __float2half_rn(v.y);
        dst[(nb + 2) * 520 + k] = __float2half_rn(v.z);
        dst[(nb + 3) * 520 + k] = __float2half_rn(v.w);
    }
    __syncthreads();
    uint32_t breg[4][16][2];
    #pragma unroll
    for (int nt = 0; nt < 4; nt++) {
        uint32_t base = sb + OFF_AS + (wn0 + nt * 8 + l7) * 1040 + l8 * 16 + kh * 512;
        #pragma unroll
        for (int ks = 0; ks < 16; ks++)
            ldsm2(breg[nt][ks], base + ks * 32);
    }
    __syncthreads();

    // ---- init 2: Wh2 slice -> Wh2s (n-major fp16); Wx2 slice -> OFF_WX ----
    #pragma unroll 4
    for (int i = 0; i < 32; i++) {
        int f4 = tid + i * 256;
        int k = f4 >> 4, rem = f4 & 15, g = rem >> 2, q = rem & 3;
        float4 v = *(const float4*)(Wh2 + ((size_t)g * Hsz + k) * Hsz + h0 + q * 4);
        int nb = g * 16 + q * 4;
        Wh2s[(nb + 0) * 520 + k] = __float2half_rn(v.x);
        Wh2s[(nb + 1) * 520 + k] = __float2half_rn(v.y);
        Wh2s[(nb + 2) * 520 + k] = __float2half_rn(v.z);
        Wh2s[(nb + 3) * 520 + k] = __float2half_rn(v.w);
    }
    #pragma unroll
    for (int i = 0; i < 16; i++) {
        int idx = tid + i * 256;
        int n = idx >> 6, q = idx & 63;
        int g = n >> 4, hh = n & 15;
        cp16(sb + OFF_WX + n * 1040 + q * 16,
             W2T + ((size_t)g * Hsz + h0 + hh) * 512 + q * 8);
    }
    CP_COMMIT();
    CP_WAIT(0);
    __syncthreads();

    // t-invariant fragment addresses
    uint32_t abase[2], bbase2[4];
    #pragma unroll
    for (int mt = 0; mt < 2; mt++)
        abase[mt] = sb + OFF_AS + (wm0 + mt * 16 + l7 + l8 * 8) * 1040 + l16 * 16 + kh * 512;
    #pragma unroll
    for (int nt = 0; nt < 4; nt++)
        bbase2[nt] = sb + (wn0 + nt * 8 + l7) * 1040 + l8 * 16 + kh * 512;

    // producer: full-K tiling
    const int wn0p = (wid >> 1) * 16;
    uint32_t pabase[2], pxbase[2];
    int gc2[2];
    float2 bsv2[2];
    #pragma unroll
    for (int mt = 0; mt < 2; mt++)
        pabase[mt] = sb + OFF_AS + (wm0 + mt * 16 + l7 + l8 * 8) * 1040 + l16 * 16;
    #pragma unroll
    for (int nt = 0; nt < 2; nt++) {
        pxbase[nt] = sb + OFF_WX + (wn0p + nt * 8 + l7) * 1040 + l8 * 16;
        int n = wn0p + nt * 8 + tig * 2;
        int g = n >> 4, hh = n & 15;
        gc2[nt] = g * Hsz + h0 + hh;
        bsv2[nt] = make_float2(bias2[gc2[nt]], bias2[gc2[nt] + 1]);
    }

    const int rr = tid >> 2;
    const int hq = (tid & 3) * 4;
    float cr1[4] = {0.f, 0.f, 0.f, 0.f};
    float cr2[4] = {0.f, 0.f, 0.f, 0.f};

    auto stageA_issue = [&](const __half* hp) {
        #pragma unroll
        for (int i = 0; i < 16; i++) {
            int f4 = tid + i * 256;
            int row = f4 >> 6, u = f4 & 63;
            cp16(sb + OFF_AS + row * 1040 + u * 16, hp + (size_t)row * Hsz + u * 8);
        }
        CP_COMMIT();
    };

    auto zstage = [&](float (*acc)[4]) {
        #pragma unroll
        for (int u = 0; u < 8; u++) {
            int mt = u >> 2, nt = u & 3;
            int row = wm0 + mt * 16 + gid, col = wn0 + nt * 8 + tig * 2;
            if (kh == 0) {
                *(float2*)&zs0[row * PZ + col]       = make_float2(acc[u][0], acc[u][1]);
                *(float2*)&zs0[(row + 8) * PZ + col] = make_float2(acc[u][2], acc[u][3]);
            } else {
                *(__half2*)&zs1[row * PZ1 + col]       = __floats2half2_rn(acc[u][0], acc[u][1]);
                *(__half2*)&zs1[(row + 8) * PZ1 + col] = __floats2half2_rn(acc[u][2], acc[u][3]);
            }
        }
    };

    // gates on zs + zxu -> cr + fp16 out
    auto gates = [&](uint2* zxu, float* cr, __half* hout) {
        const float* z0 = &zs0[rr * PZ];
        const __half* z1 = &zs1[rr * PZ1];
        float zxa[4][4];
        #pragma unroll
        for (int g = 0; g < 4; g++) {
            __half2* zh = (__half2*)&zxu[g];
            float2 lo = __half22float2(zh[0]);
            float2 hi = __half22float2(zh[1]);
            zxa[g][0] = lo.x; zxa[g][1] = lo.y; zxa[g][2] = hi.x; zxa[g][3] = hi.y;
        }
        __half hv[4];
        #pragma unroll
        for (int j = 0; j < 4; j++) {
            float zg = z0[hq + j]      + __half2float(z1[hq + j])      + zxa[0][j];
            float zi = z0[16 + hq + j] + __half2float(z1[16 + hq + j]) + zxa[1][j];
            float zf = z0[32 + hq + j] + __half2float(z1[32 + hq + j]) + zxa[2][j];
            float zo = z0[48 + hq + j] + __half2float(z1[48 + hq + j]) + zxa[3][j];
            float gg = tanha(zg);
            float ii = sigf(zi);
            float ff = sigf(zf);
            float oo = sigf(zo);
            float cn = __fmaf_rn(gg, ii, cr[j] * ff);
            cr[j] = cn;
            hv[j] = __float2half_rn(tanha(cn) * oo);
        }
        *(uint2*)hout = *(uint2*)hv;
    };

    #pragma unroll 1
    for (int e = 0; e <= 257; e++) {
        if (e > 0) {
            if (tid == 0) bar_spin(&bar[grp], 32u * (unsigned)e);
            __syncthreads();
        }

        const bool do1 = (e <= 255);
        const bool dop = (e >= 1 && e <= 256);
        const bool do2 = (e >= 2);

        // stage A <- h1(e); Zx1 prefetch rides the cp.async flight
        uint2 zxu1[4];
        if (e <= 256) {
            stageA_issue(h1s + (size_t)e * (Bsz * Hsz) + (size_t)m0 * Hsz);
            if (do1) {
                const __half* zxp = Zx1 + (size_t)e * (Bsz * NG) + (size_t)(m0 + rr) * NG + h0 + hq;
                #pragma unroll
                for (int g = 0; g < 4; g++) zxu1[g] = __ldcs((const uint2*)(zxp + g * Hsz));
            }
            CP_WAIT(0);
            __syncthreads();
        }

        // layer 1 step e
        if (do1) {
            float acc[8][4] = {};
            #pragma unroll
            for (int ks = 0; ks < 16; ks++) {
                uint32_t a[2][4];
                ldsm4(a[0], abase[0] + ks * 32);
                ldsm4(a[1], abase[1] + ks * 32);
                #pragma unroll
                for (int mt = 0; mt < 2; mt++)
                    #pragma unroll
                    for (int nt = 0; nt < 4; nt++)
                        mma16(acc[mt * 4 + nt], a[mt], breg[nt][ks]);
            }
            zstage(acc);
            __syncthreads();
            gates(zxu1, cr1,
                  h1s + (size_t)(e + 1) * (Bsz * Hsz) + (size_t)(m0 + rr) * Hsz + h0 + hq);
        }

        // producer: Zx2(e-1) from staged h1(e) — exact R12 ordering (mma then stores)
        if (dop) {
            float za[4][4] = {};
            #pragma unroll 8
            for (int ks = 0; ks < 32; ks++) {
                uint32_t a[2][4], b[2][2];
                ldsm4(a[0], pabase[0] + ks * 32);
                ldsm4(a[1], pabase[1] + ks * 32);
                ldsm2(b[0], pxbase[0] + ks * 32);
                ldsm2(b[1], pxbase[1] + ks * 32);
                mma16(za[0], a[0], b[0]); mma16(za[1], a[0], b[1]);
                mma16(za[2], a[1], b[0]); mma16(za[3], a[1], b[1]);
            }
            __half* zb = Zx2 + ((size_t)(e - 1) * Bsz + m0) * NG;
            #pragma unroll
            for (int u = 0; u < 4; u++) {
                int mt = u >> 1, nt = u & 1;
                int row = wm0 + mt * 16 + gid;
                *(__half2*)&zb[(size_t)row * NG + gc2[nt]] =
                    __floats2half2_rn(za[u][0] + bsv2[nt].x, za[u][1] + bsv2[nt].y);
                *(__half2*)&zb[(size_t)(row + 8) * NG + gc2[nt]] =
                    __floats2half2_rn(za[u][2] + bsv2[nt].x, za[u][3] + bsv2[nt].y);
            }
        }
        __syncthreads();   // A + zs consumers done

        // layer 2 step e-2: Zx2 prefetch rides the h2-stage flight
        if (do2) {
            stageA_issue(h2s + (size_t)(e - 2) * (Bsz * Hsz) + (size_t)m0 * Hsz);
            uint2 zxu2[4];
            const __half* zxp = Zx2 + (size_t)(e - 2) * (Bsz * NG) + (size_t)(m0 + rr) * NG + h0 + hq;
            #pragma unroll
            for (int g = 0; g < 4; g++) zxu2[g] = __ldcg((const uint2*)(zxp + g * Hsz));
            CP_WAIT(0);
            __syncthreads();

            float acc[8][4] = {};
            #pragma unroll
            for (int ks = 0; ks < 16; ks++) {
                uint32_t a[2][4], b[4][2];
                ldsm4(a[0], abase[0] + ks * 32);
                ldsm4(a[1], abase[1] + ks * 32);
                #pragma unroll
                for (int nt = 0; nt < 4; nt++) ldsm2(b[nt], bbase2[nt] + ks * 32);
                #pragma unroll
                for (int mt = 0; mt < 2; mt++)
                    #pragma unroll
                    for (int nt = 0; nt < 4; nt++)
                        mma16(acc[mt * 4 + nt], a[mt], b[nt]);
            }
            zstage(acc);
            __syncthreads();
            gates(zxu2, cr2,
                  h2s + (size_t)(e - 1) * (Bsz * Hsz) + (size_t)(m0 + rr) * Hsz + h0 + hq);
        }

        if (e < 257) {
            __syncthreads();
            if (tid == 0) bar_arrive(&bar[grp]);
        }
    }
}

// ---------------- final projection ----------------
__global__ void proj_kernel(const __half* __restrict__ h2,
                            const float* __restrict__ Wph,
                            const float* __restrict__ bp,
                            float* __restrict__ out) {
    int idx = blockIdx.x * blockDim.x + threadIdx.x;
    if (idx >= Bsz * Csz) return;
    int b = idx / Csz, cc = idx % Csz;
    float s = bp[cc];
    for (int k = 0; k < Hsz; k++)
        s += __half2float(h2[(size_t)b * Hsz + k]) * Wph[(size_t)k * Csz + cc];
    out[idx] = s;
}

// ---------------- launch ----------------
extern "C" void kernel_launch(void* const* d_in, const int* in_sizes, int n_in,
                              void* d_out, int out_size) {
    const float* x   = (const float*)d_in[0];
    const float* Wx1 = (const float*)d_in[1];
    const float* Wh1 = (const float*)d_in[2];
    const float* b1  = (const float*)d_in[3];
    const float* Wx2 = (const float*)d_in[4];
    const float* Wh2 = (const float*)d_in[5];
    const float* b2  = (const float*)d_in[6];
    const float* Wph = (const float*)d_in[7];
    const float* bp  = (const float*)d_in[8];
    float* out = (float*)d_out;

    __half *Zx1, *Zx2, *h1, *h2, *xT, *W1T, *W2T;
    unsigned* bar;
    cudaGetSymbolAddress((void**)&Zx1, g_Zx1);
    cudaGetSymbolAddress((void**)&Zx2, g_Zx2);
    cudaGetSymbolAddress((void**)&h1,  g_h1);
    cudaGetSymbolAddress((void**)&h2,  g_h2);
    cudaGetSymbolAddress((void**)&xT,  g_xT);
    cudaGetSymbolAddress((void**)&W1T, g_W1T);
    cudaGetSymbolAddress((void**)&W2T, g_W2T);
    cudaGetSymbolAddress((void**)&bar, g_bar);

    cudaFuncSetAttribute(lstm_fused, cudaFuncAttributeMaxDynamicSharedMemorySize, PSM);
    cudaFuncSetAttribute(gemm_h2, cudaFuncAttributeMaxDynamicSharedMemorySize, GSM);

    init_kernel<<<(Bsz * Hsz + 255) / 256, 256>>>();

    prep_x<<<(Tt * Bsz * 16 + 255) / 256, 256>>>(x, xT);
    prep_w<<<(4 * Hsz * (Isz / 2) + 255) / 256, 256>>>(Wx1, W1T, Isz);
    prep_w<<<(4 * Hsz * (Hsz / 2) + 255) / 256, 256>>>(Wx2, W2T, Hsz);

    // Phase 1: Zx1 = x @ Wx1 + b1
    gemm_h2<<<dim3(NG / 128, (Tt * Bsz) / 128), 256, GSM>>>(xT, W1T, b1, Zx1, Isz);

    // Phase 2: fused 2-layer recurrence (258 epochs, R12 structure + flight-riding prefetches)
    lstm_fused<<<dim3(Hsz / 16, Bsz / 64), 256, PSM>>>(
        Zx1, Wh1, Wh2, h1, h2, bar, W2T, b2, Zx2);

    // Phase 3: projection
    proj_kernel<<<(Bsz * Csz + 255) / 256, 256>>>(
        h2 + (size_t)Tt * Bsz * Hsz, Wph, bp, out);
}